// round 1
// baseline (speedup 1.0000x reference)
#include <cuda_runtime.h>
#include <cuda_bf16.h>
#include <cstdint>

#define DEV_INLINE __device__ __forceinline__

// Problem dims (fixed by the dataset): B=2, S=2048, H=2048
constexpr int TOK = 4096;   // B*S
constexpr int H   = 2048;
constexpr int H4  = 8192;

// ---------------------------------------------------------------------------
// Scratch (device globals — no allocations allowed)
// ---------------------------------------------------------------------------
__device__ __nv_bfloat16 g_Xq [(size_t)TOK * H];   // quantized LN(x)      [4096,2048]
__device__ __nv_bfloat16 g_W1q[(size_t)H4 * H];    // quantized W1         [8192,2048]
__device__ __nv_bfloat16 g_W2q[(size_t)H * H4];    // quantized W2         [2048,8192]
__device__ __nv_bfloat16 g_H1g[(size_t)TOK * H4];  // gelu output (bf16)   [4096,8192]
__device__ __nv_bfloat16 g_H1q[(size_t)TOK * H4];  // quantized gelu out   [4096,8192]

// ---------------------------------------------------------------------------
// Helpers
// ---------------------------------------------------------------------------
DEV_INLINE float bf16r(float x) { return __bfloat162float(__float2bfloat16(x)); }

// MXINT8 fake-quant of one element given the block amax.
// scale = 2^(floor(log2(amax)) - 6); q = clip(rint(v/scale), -128, 127)*scale
DEV_INLINE float mxq(float v, float amax) {
    if (!(amax > 0.0f)) return 0.0f;
    float se    = floorf(log2f(amax));
    float inv   = exp2f(6.0f - se);   // exact powers of two
    float scale = exp2f(se - 6.0f);
    float q = rintf(v * inv);         // rint == round-half-even == jnp.round
    q = fminf(fmaxf(q, -128.0f), 127.0f);
    return q * scale;                 // exact, bf16-representable
}

DEV_INLINE float gelu_tanh_bf16(float x) {
    float x3 = x * x * x;
    float t  = tanhf(0.7978845608028654f * (x + 0.044715f * x3));
    return bf16r(0.5f * x * (1.0f + t));
}

// ---------------------------------------------------------------------------
// Weight quantization: one warp per 32-element block (K-contiguous).
// ---------------------------------------------------------------------------
template <int WHICH>  // 0 -> W1 -> g_W1q ; 1 -> W2 -> g_W2q
__global__ void quant_w_kernel(const float* __restrict__ src) {
    __nv_bfloat16* dst = (WHICH == 0) ? g_W1q : g_W2q;
    int w    = (blockIdx.x << 3) + (threadIdx.x >> 5);
    int lane = threadIdx.x & 31;
    size_t idx = ((size_t)w << 5) + lane;
    float v = src[idx];
    float a = fabsf(v);
#pragma unroll
    for (int o = 16; o; o >>= 1) a = fmaxf(a, __shfl_xor_sync(0xffffffffu, a, o));
    dst[idx] = __float2bfloat16(mxq(v, a));
}

// Quantize gelu output (bf16 -> bf16), blocks along the 8192 axis.
__global__ void quant_h1_kernel() {
    int w    = (blockIdx.x << 3) + (threadIdx.x >> 5);
    int lane = threadIdx.x & 31;
    size_t idx = ((size_t)w << 5) + lane;
    float v = __bfloat162float(g_H1g[idx]);
    float a = fabsf(v);
#pragma unroll
    for (int o = 16; o; o >>= 1) a = fmaxf(a, __shfl_xor_sync(0xffffffffu, a, o));
    g_H1q[idx] = __float2bfloat16(mxq(v, a));
}

// ---------------------------------------------------------------------------
// Fused: x = bf16(inputs); LayerNorm (fp32, two-pass); bf16 round; MX quant.
// One CTA (256 threads) per token row of H=2048.
// ---------------------------------------------------------------------------
__global__ void ln_quant_kernel(const float* __restrict__ x,
                                const float* __restrict__ w,
                                const float* __restrict__ b) {
    __shared__ float red[8];
    __shared__ __nv_bfloat16 sn[H];
    int row = blockIdx.x;
    int tid = threadIdx.x;
    const float* xr = x + (size_t)row * H;

    float v[8];
    float s = 0.0f;
#pragma unroll
    for (int j = 0; j < 8; j++) {
        v[j] = bf16r(xr[tid + j * 256]);
        s += v[j];
    }
#pragma unroll
    for (int o = 16; o; o >>= 1) s += __shfl_xor_sync(0xffffffffu, s, o);
    if ((tid & 31) == 0) red[tid >> 5] = s;
    __syncthreads();
    float tot = 0.0f;
#pragma unroll
    for (int i = 0; i < 8; i++) tot += red[i];
    float mu = tot * (1.0f / H);
    __syncthreads();

    float s2 = 0.0f;
#pragma unroll
    for (int j = 0; j < 8; j++) { float d = v[j] - mu; s2 += d * d; }
#pragma unroll
    for (int o = 16; o; o >>= 1) s2 += __shfl_xor_sync(0xffffffffu, s2, o);
    if ((tid & 31) == 0) red[tid >> 5] = s2;
    __syncthreads();
    float tot2 = 0.0f;
#pragma unroll
    for (int i = 0; i < 8; i++) tot2 += red[i];
    float var = tot2 * (1.0f / H);
    float rs = rsqrtf(var + 1e-5f);

#pragma unroll
    for (int j = 0; j < 8; j++) {
        int idx = tid + j * 256;
        float nv = (v[j] - mu) * rs * w[idx] + b[idx];
        sn[idx] = __float2bfloat16(nv);
    }
    __syncthreads();

    // MX quant: 64 blocks of 32; warp wp handles blocks wp*8 .. wp*8+7
    int wp = tid >> 5, lane = tid & 31;
    __nv_bfloat16* orow = g_Xq + (size_t)row * H;
#pragma unroll
    for (int i = 0; i < 8; i++) {
        int e = (wp * 8 + i) * 32 + lane;
        float val = __bfloat162float(sn[e]);
        float a = fabsf(val);
#pragma unroll
        for (int o = 16; o; o >>= 1) a = fmaxf(a, __shfl_xor_sync(0xffffffffu, a, o));
        orow[e] = __float2bfloat16(mxq(val, a));
    }
}

// ---------------------------------------------------------------------------
// GEMM: C[M,N] = sum_k A[m,k]*B[n,k], bf16 inputs, fp32 accumulate.
// CTA tile 128x128x32, double-buffered cp.async, mma.sync.m16n8k16.
// PHASE 1: A=g_Xq[4096,2048], B=g_W1q[8192,2048]; epilogue +b1, bf16, gelu,
//          bf16 -> g_H1g.
// PHASE 2: A=g_H1q[4096,8192], B=g_W2q[2048,8192]; epilogue +b2, bf16,
//          + bf16(resid), bf16 -> out (f32).
// ---------------------------------------------------------------------------
constexpr int BM = 128, BN = 128, BK = 32;
constexpr int LDK = 48;  // padded smem row stride (elements), 96B (16B aligned)

DEV_INLINE void cp16(void* dst_s, const void* src_g) {
    unsigned d = (unsigned)__cvta_generic_to_shared(dst_s);
    asm volatile("cp.async.cg.shared.global [%0], [%1], 16;\n" ::"r"(d), "l"(src_g));
}

template <int PHASE>
__global__ __launch_bounds__(256) void gemm_kernel(const float* __restrict__ bias,
                                                   const float* __restrict__ resid,
                                                   float* __restrict__ outf) {
    constexpr int N = (PHASE == 1) ? H4 : H;
    constexpr int K = (PHASE == 1) ? H : H4;
    const __nv_bfloat16* __restrict__ A  = (PHASE == 1) ? g_Xq  : g_H1q;
    const __nv_bfloat16* __restrict__ Bm = (PHASE == 1) ? g_W1q : g_W2q;

    __shared__ __nv_bfloat16 sA[2][BM][LDK];
    __shared__ __nv_bfloat16 sB[2][BN][LDK];

    int tid = threadIdx.x;
    int m0 = blockIdx.y * BM, n0 = blockIdx.x * BN;

    int warp = tid >> 5, lane = tid & 31;
    int wm = warp & 3, wn = warp >> 2;     // 4 x 2 warps -> 32x64 warp tiles
    int gr = lane >> 2, gc = (lane & 3) * 2;

    float acc[2][8][4];
#pragma unroll
    for (int a = 0; a < 2; a++)
#pragma unroll
        for (int b = 0; b < 8; b++)
#pragma unroll
            for (int c = 0; c < 4; c++) acc[a][b][c] = 0.0f;

    constexpr int NT = K / BK;

    // tile loader: 512 16B chunks per operand, 2 per thread per operand
    auto load_tile = [&](int buf, int kt) {
        int k0 = kt * BK;
#pragma unroll
        for (int i = 0; i < 2; i++) {
            int c = tid + i * 256;
            int row = c >> 2, kc = (c & 3) * 8;
            cp16(&sA[buf][row][kc], A + (size_t)(m0 + row) * K + k0 + kc);
            cp16(&sB[buf][row][kc], Bm + (size_t)(n0 + row) * K + k0 + kc);
        }
        asm volatile("cp.async.commit_group;\n");
    };

    load_tile(0, 0);

    for (int kt = 0; kt < NT; kt++) {
        asm volatile("cp.async.wait_group 0;\n");
        __syncthreads();
        if (kt + 1 < NT) load_tile((kt + 1) & 1, kt + 1);
        int buf = kt & 1;
#pragma unroll
        for (int ks = 0; ks < 2; ks++) {
            uint32_t af[2][4];
#pragma unroll
            for (int mt = 0; mt < 2; mt++) {
                int r = wm * 32 + mt * 16;
                af[mt][0] = *(const uint32_t*)(&sA[buf][r + gr][ks * 16 + gc]);
                af[mt][1] = *(const uint32_t*)(&sA[buf][r + gr + 8][ks * 16 + gc]);
                af[mt][2] = *(const uint32_t*)(&sA[buf][r + gr][ks * 16 + gc + 8]);
                af[mt][3] = *(const uint32_t*)(&sA[buf][r + gr + 8][ks * 16 + gc + 8]);
            }
#pragma unroll
            for (int nt = 0; nt < 8; nt++) {
                int nr = wn * 64 + nt * 8 + gr;
                uint32_t b0 = *(const uint32_t*)(&sB[buf][nr][ks * 16 + gc]);
                uint32_t b1 = *(const uint32_t*)(&sB[buf][nr][ks * 16 + gc + 8]);
#pragma unroll
                for (int mt = 0; mt < 2; mt++) {
                    asm volatile(
                        "mma.sync.aligned.m16n8k16.row.col.f32.bf16.bf16.f32 "
                        "{%0,%1,%2,%3}, {%4,%5,%6,%7}, {%8,%9}, {%0,%1,%2,%3};\n"
                        : "+f"(acc[mt][nt][0]), "+f"(acc[mt][nt][1]),
                          "+f"(acc[mt][nt][2]), "+f"(acc[mt][nt][3])
                        : "r"(af[mt][0]), "r"(af[mt][1]), "r"(af[mt][2]), "r"(af[mt][3]),
                          "r"(b0), "r"(b1));
                }
            }
        }
        __syncthreads();
    }

    // Epilogue
#pragma unroll
    for (int mt = 0; mt < 2; mt++) {
        int r0 = m0 + wm * 32 + mt * 16 + gr;
#pragma unroll
        for (int nt = 0; nt < 8; nt++) {
            int c0 = n0 + wn * 64 + nt * 8 + gc;
            float2 bb = *(const float2*)(bias + c0);
#pragma unroll
            for (int hh = 0; hh < 2; hh++) {
                int r = r0 + hh * 8;
                float y0 = acc[mt][nt][hh * 2 + 0] + bb.x;
                float y1 = acc[mt][nt][hh * 2 + 1] + bb.y;
                if (PHASE == 1) {
                    float g0 = gelu_tanh_bf16(bf16r(y0));
                    float g1 = gelu_tanh_bf16(bf16r(y1));
                    __nv_bfloat162 p;
                    p.x = __float2bfloat16(g0);
                    p.y = __float2bfloat16(g1);
                    *(__nv_bfloat162*)(&g_H1g[(size_t)r * N + c0]) = p;
                } else {
                    float h0 = bf16r(y0), h1 = bf16r(y1);
                    float2 rv = *(const float2*)(resid + (size_t)r * N + c0);
                    float o0 = bf16r(bf16r(rv.x) + h0);
                    float o1 = bf16r(bf16r(rv.y) + h1);
                    *(float2*)(&outf[(size_t)r * N + c0]) = make_float2(o0, o1);
                }
            }
        }
    }
}

// ---------------------------------------------------------------------------
// Launch
// ---------------------------------------------------------------------------
extern "C" void kernel_launch(void* const* d_in, const int* in_sizes, int n_in,
                              void* d_out, int out_size) {
    const float* inputs = (const float*)d_in[0];  // [2,2048,2048]
    const float* ln_w   = (const float*)d_in[1];  // [2048]
    const float* ln_b   = (const float*)d_in[2];  // [2048]
    const float* W1     = (const float*)d_in[3];  // [8192,2048]
    const float* b1     = (const float*)d_in[4];  // [8192]
    const float* W2     = (const float*)d_in[5];  // [2048,8192]
    const float* b2     = (const float*)d_in[6];  // [2048]
    float* out = (float*)d_out;                   // [2,2048,2048] f32

    // 1) quantize weights (W1: 524288 blocks, W2: 524288 blocks)
    quant_w_kernel<0><<<(H4 * H / 32) / 8, 256>>>(W1);
    quant_w_kernel<1><<<(H * H4 / 32) / 8, 256>>>(W2);

    // 2) bf16-round + layernorm + MX-quant activations
    ln_quant_kernel<<<TOK, 256>>>(inputs, ln_w, ln_b);

    // 3) GEMM1 (+b1, bf16, gelu, bf16) -> g_H1g
    gemm_kernel<1><<<dim3(H4 / BN, TOK / BM), 256>>>(b1, nullptr, nullptr);

    // 4) MX-quant gelu output along 8192 axis -> g_H1q
    quant_h1_kernel<<<((size_t)TOK * H4 / 32) / 8, 256>>>();

    // 5) GEMM2 (+b2, bf16, +bf16(residual), bf16) -> out (f32)
    gemm_kernel<2><<<dim3(H / BN, TOK / BM), 256>>>(b2, inputs, out);
}